// round 14
// baseline (speedup 1.0000x reference)
#include <cuda_runtime.h>
#include <cuda_fp16.h>

#define INPUT_DIM 20000
#define UNITS     4096
#define NNZ       800000
#define BATCH     1024
#define CAP       320          // max nnz per column (Poisson(195), 9-sigma headroom)
#define NB_SCAT   391          // ceil(NNZ / 8 / 256) scatter blocks
#define SPMM_GRID 1480         // 148 SMs x 10 CTAs: one full wave, persistent loop

// ---------------- scratch (no allocations allowed) ----------------
__device__ int    g_col_cnt[UNITS];                  // bucket fill counters
__device__ int2   g_rv[(size_t)UNITS * CAP];         // fixed-stride buckets, 10.5 MB
__device__ __half g_xT[(size_t)INPUT_DIM * BATCH];   // 41 MB, L2-resident
__device__ float  g_outT[(size_t)UNITS * BATCH];     // 16.8 MB

// ---------------- 1. fused prologue: scatter blocks + transpose tiles ------------
__device__ __forceinline__ int pack_h2(float v) {
    unsigned short h = __half_as_ushort(__float2half_rn(v));
    return (int)(((unsigned)h << 16) | (unsigned)h);
}

__device__ __forceinline__ void put(int col, int row, float v) {
    int p = atomicAdd(&g_col_cnt[col], 1);
    if (p < CAP) g_rv[(size_t)col * CAP + p] = make_int2(row, pack_h2(v));
}

__global__ void __launch_bounds__(256) k_prologue(const float* __restrict__ x,
                                                  const int*   __restrict__ nz,
                                                  const float* __restrict__ vals) {
    const int tid  = threadIdx.y * 32 + threadIdx.x;

    if (blockIdx.x < NB_SCAT) {
        // ---- scatter into fixed-stride buckets: 8 nnz/thread ----
        int i0 = (blockIdx.x * 256 + tid) * 8;
        if (i0 + 7 < NNZ) {
            int4 a = *reinterpret_cast<const int4*>(&nz[2 * i0]);
            int4 b = *reinterpret_cast<const int4*>(&nz[2 * i0 + 4]);
            int4 c = *reinterpret_cast<const int4*>(&nz[2 * i0 + 8]);
            int4 d = *reinterpret_cast<const int4*>(&nz[2 * i0 + 12]);
            float4 v0 = *reinterpret_cast<const float4*>(&vals[i0]);
            float4 v1 = *reinterpret_cast<const float4*>(&vals[i0 + 4]);
            put(a.y, a.x, v0.x);
            put(a.w, a.z, v0.y);
            put(b.y, b.x, v0.z);
            put(b.w, b.z, v0.w);
            put(c.y, c.x, v1.x);
            put(c.w, c.z, v1.y);
            put(d.y, d.x, v1.z);
            put(d.w, d.z, v1.w);
        } else {
            for (int i = i0; i < NNZ; i++)
                put(nz[2 * i + 1], nz[2 * i], vals[i]);
        }
    } else {
        // ---- transpose tile: x [B,K] fp32 -> xT [K,B] fp16 ----
        __shared__ float s[32][65];      // pad 65: float4 fan-out hits 32 banks
        const int lane = tid & 31;
        const int w    = tid >> 5;       // 8 warps
        int tb = blockIdx.x - NB_SCAT;
        int rb = (tb % 625) * 32;        // input-dim base
        int bb = (tb / 625) * 64;        // batch base (1024/64 = 16)
#pragma unroll
        for (int h = 0; h < 2; h++) {
            int idx = tid + h * 256;     // 0..511
            int q   = idx & 7;           // k-chunk (4 floats)
            int b   = idx >> 3;          // batch row 0..63
            float4 v = *reinterpret_cast<const float4*>(
                &x[(size_t)(bb + b) * INPUT_DIM + rb + 4 * q]);
            s[4 * q + 0][b] = v.x;
            s[4 * q + 1][b] = v.y;
            s[4 * q + 2][b] = v.z;
            s[4 * q + 3][b] = v.w;
        }
        __syncthreads();
#pragma unroll
        for (int j = 0; j < 4; j++) {
            int row = w + j * 8;
            int b0  = lane * 2;
            __half2 h = __floats2half2_rn(s[row][b0], s[row][b0 + 1]);
            *reinterpret_cast<__half2*>(&g_xT[(size_t)(rb + row) * BATCH + bb + b0]) = h;
        }
    }
}

// ------- 2. spmm: R12 hot loop (128 thr, uint4), persistent column loop ----------
#define LOADQ(Q01, Q23, J)                                             \
    Q01 = *reinterpret_cast<int4*>(&s_rv[J]);                          \
    Q23 = *reinterpret_cast<int4*>(&s_rv[(J) + 2]);

#define LOADD(D0, D1, D2, D3, Q01, Q23)                                \
    D0 = xp[Q01.x * (BATCH / 8) + t];                                  \
    D1 = xp[Q01.z * (BATCH / 8) + t];                                  \
    D2 = xp[Q23.x * (BATCH / 8) + t];                                  \
    D3 = xp[Q23.z * (BATCH / 8) + t];

#define FMAG(Q01, Q23, D0, D1, D2, D3)                                        \
    {                                                                         \
        __half2 v0 = *reinterpret_cast<__half2*>(&Q01.y);                     \
        __half2 v1 = *reinterpret_cast<__half2*>(&Q01.w);                     \
        __half2 v2 = *reinterpret_cast<__half2*>(&Q23.y);                     \
        __half2 v3 = *reinterpret_cast<__half2*>(&Q23.w);                     \
        __half2 px = __hmul2(*reinterpret_cast<__half2*>(&D0.x), v0);         \
        __half2 py = __hmul2(*reinterpret_cast<__half2*>(&D0.y), v0);         \
        __half2 pz = __hmul2(*reinterpret_cast<__half2*>(&D0.z), v0);         \
        __half2 pw = __hmul2(*reinterpret_cast<__half2*>(&D0.w), v0);         \
        px = __hfma2(*reinterpret_cast<__half2*>(&D1.x), v1, px);             \
        py = __hfma2(*reinterpret_cast<__half2*>(&D1.y), v1, py);             \
        pz = __hfma2(*reinterpret_cast<__half2*>(&D1.z), v1, pz);             \
        pw = __hfma2(*reinterpret_cast<__half2*>(&D1.w), v1, pw);             \
        px = __hfma2(*reinterpret_cast<__half2*>(&D2.x), v2, px);             \
        py = __hfma2(*reinterpret_cast<__half2*>(&D2.y), v2, py);             \
        pz = __hfma2(*reinterpret_cast<__half2*>(&D2.z), v2, pz);             \
        pw = __hfma2(*reinterpret_cast<__half2*>(&D2.w), v2, pw);             \
        px = __hfma2(*reinterpret_cast<__half2*>(&D3.x), v3, px);             \
        py = __hfma2(*reinterpret_cast<__half2*>(&D3.y), v3, py);             \
        pz = __hfma2(*reinterpret_cast<__half2*>(&D3.z), v3, pz);             \
        pw = __hfma2(*reinterpret_cast<__half2*>(&D3.w), v3, pw);             \
        float2 fx = __half22float2(px);                                       \
        float2 fy = __half22float2(py);                                       \
        float2 fz = __half22float2(pz);                                       \
        float2 fw = __half22float2(pw);                                       \
        unsigned long long w0, w1, w2, w3;                                    \
        asm("mov.b64 %0, {%1, %2};" : "=l"(w0) : "f"(fx.x), "f"(fx.y));       \
        asm("mov.b64 %0, {%1, %2};" : "=l"(w1) : "f"(fy.x), "f"(fy.y));       \
        asm("mov.b64 %0, {%1, %2};" : "=l"(w2) : "f"(fz.x), "f"(fz.y));       \
        asm("mov.b64 %0, {%1, %2};" : "=l"(w3) : "f"(fw.x), "f"(fw.y));       \
        asm("add.rn.f32x2 %0, %0, %1;" : "+l"(a0) : "l"(w0));                 \
        asm("add.rn.f32x2 %0, %0, %1;" : "+l"(a1) : "l"(w1));                 \
        asm("add.rn.f32x2 %0, %0, %1;" : "+l"(a2) : "l"(w2));                 \
        asm("add.rn.f32x2 %0, %0, %1;" : "+l"(a3) : "l"(w3));                 \
    }

__global__ void __launch_bounds__(128) k_spmm(const float* __restrict__ bias) {
    const int t = threadIdx.x;
    __shared__ int2 s_rv[256];
    const uint4* __restrict__ xp = reinterpret_cast<const uint4*>(g_xT);

    for (int u = blockIdx.x; u < UNITS; u += SPMM_GRID) {
        const int cnt = min(g_col_cnt[u], CAP);
        const int2* __restrict__ bucket = &g_rv[(size_t)u * CAP];

        unsigned long long a0 = 0, a1 = 0, a2 = 0, a3 = 0;   // packed f32x2 acc

        for (int base = 0; base < cnt; base += 256) {
            int n = cnt - base;
            s_rv[t]       = (t < n)       ? bucket[base + t]       : make_int2(0, 0);
            s_rv[t + 128] = (t + 128 < n) ? bucket[base + t + 128] : make_int2(0, 0);
            __syncthreads();
            int mc = (min(256, n) + 7) & ~7;  // multiple of 8; pads contribute 0

            int4  qA01, qA23, qB01, qB23;
            uint4 dA0, dA1, dA2, dA3, dB0, dB1, dB2, dB3;
            LOADQ(qA01, qA23, 0)
            LOADD(dA0, dA1, dA2, dA3, qA01, qA23)
            for (int i = 0; i < mc; i += 8) {
                LOADQ(qB01, qB23, i + 4)
                LOADD(dB0, dB1, dB2, dB3, qB01, qB23)
                FMAG(qA01, qA23, dA0, dA1, dA2, dA3)
                int ja = (i + 8) & 255;       // s_rv fully initialized, safe
                LOADQ(qA01, qA23, ja)
                LOADD(dA0, dA1, dA2, dA3, qA01, qA23)
                FMAG(qB01, qB23, dB0, dB1, dB2, dB3)
            }
            __syncthreads();
        }

        float b = bias[u];
        float2 f0, f1, f2, f3;
        asm("mov.b64 {%0, %1}, %2;" : "=f"(f0.x), "=f"(f0.y) : "l"(a0));
        asm("mov.b64 {%0, %1}, %2;" : "=f"(f1.x), "=f"(f1.y) : "l"(a1));
        asm("mov.b64 {%0, %1}, %2;" : "=f"(f2.x), "=f"(f2.y) : "l"(a2));
        asm("mov.b64 {%0, %1}, %2;" : "=f"(f3.x), "=f"(f3.y) : "l"(a3));
        float4 o0, o1;
        o0.x = tanhf(f0.x + b);  o0.y = tanhf(f0.y + b);
        o0.z = tanhf(f1.x + b);  o0.w = tanhf(f1.y + b);
        o1.x = tanhf(f2.x + b);  o1.y = tanhf(f2.y + b);
        o1.z = tanhf(f3.x + b);  o1.w = tanhf(f3.y + b);
        float* op = &g_outT[(size_t)u * BATCH + t * 8];
        *reinterpret_cast<float4*>(op)     = o0;
        *reinterpret_cast<float4*>(op + 4) = o1;
    }
}

// ---------------- 3. transpose outT [U,B] -> out [B,U] ----------------
__global__ void __launch_bounds__(256) k_txpose_out(float* __restrict__ out) {
    __shared__ float s[32][33];
    int ub = blockIdx.x * 32;
    int bb = blockIdx.y * 32;
    int tx = threadIdx.x, ty = threadIdx.y;
#pragma unroll
    for (int j = 0; j < 32; j += 8)
        s[ty + j][tx] = g_outT[(size_t)(ub + ty + j) * BATCH + bb + tx];
    __syncthreads();
#pragma unroll
    for (int j = 0; j < 32; j += 8)
        out[(size_t)(bb + ty + j) * UNITS + ub + tx] = s[tx][ty + j];
}

// ---------------- launch ----------------
extern "C" void kernel_launch(void* const* d_in, const int* in_sizes, int n_in,
                              void* d_out, int out_size) {
    const float* x    = (const float*)d_in[0];
    const float* kv   = (const float*)d_in[1];
    const float* bias = (const float*)d_in[2];
    const int*   nz   = (const int*)d_in[3];
    float* out = (float*)d_out;

    // zero bucket counters via a capturable memset node
    void* cnt_ptr = nullptr;
    cudaGetSymbolAddress(&cnt_ptr, g_col_cnt);
    cudaMemsetAsync(cnt_ptr, 0, UNITS * sizeof(int));

    dim3 tb(32, 8);
    k_prologue<<<NB_SCAT + 625 * (BATCH / 64), tb>>>(x, nz, kv);
    k_spmm<<<SPMM_GRID, 128>>>(bias);
    k_txpose_out<<<dim3(UNITS / 32, BATCH / 32), tb>>>(out);
}

// round 15
// speedup vs baseline: 1.2625x; 1.2625x over previous
#include <cuda_runtime.h>
#include <cuda_fp16.h>

#define INPUT_DIM 20000
#define UNITS     4096
#define NNZ       800000
#define BATCH     1024
#define CAP       320          // max nnz per column (Poisson(195), 9-sigma headroom)
#define NB_TXP    10000        // 625 * 16 transpose tiles (blocks [0, NB_TXP))
#define NB_SCAT   391          // ceil(NNZ / 8 / 256) scatter blocks (tail of grid)

// ---------------- scratch (no allocations allowed) ----------------
__device__ int    g_col_cnt[UNITS];                  // bucket fill counters
__device__ int2   g_rv[(size_t)UNITS * CAP];         // fixed-stride buckets, 10.5 MB
__device__ __half g_xT[(size_t)INPUT_DIM * BATCH];   // 41 MB, L2-resident
__device__ float  g_outT[(size_t)UNITS * BATCH];     // 16.8 MB

// ---------------- 1. fused prologue: transpose tiles + tail scatter --------------
// blocks [0, NB_TXP): 32 input-rows x 64 batch transpose tiles (DRAM-stream)
// blocks [NB_TXP, NB_TXP + NB_SCAT): bucket scatter (latency-bound, fills tail wave)
__device__ __forceinline__ int pack_h2(float v) {
    unsigned short h = __half_as_ushort(__float2half_rn(v));
    return (int)(((unsigned)h << 16) | (unsigned)h);
}

__device__ __forceinline__ void put(int col, int row, float v) {
    int p = atomicAdd(&g_col_cnt[col], 1);
    if (p < CAP) g_rv[(size_t)col * CAP + p] = make_int2(row, pack_h2(v));
}

__global__ void __launch_bounds__(256) k_prologue(const float* __restrict__ x,
                                                  const int*   __restrict__ nz,
                                                  const float* __restrict__ vals) {
    const int tid  = threadIdx.y * 32 + threadIdx.x;

    if (blockIdx.x >= NB_TXP) {
        // ---- scatter into fixed-stride buckets: 8 nnz/thread ----
        int i0 = ((blockIdx.x - NB_TXP) * 256 + tid) * 8;
        if (i0 + 7 < NNZ) {
            int4 a = *reinterpret_cast<const int4*>(&nz[2 * i0]);
            int4 b = *reinterpret_cast<const int4*>(&nz[2 * i0 + 4]);
            int4 c = *reinterpret_cast<const int4*>(&nz[2 * i0 + 8]);
            int4 d = *reinterpret_cast<const int4*>(&nz[2 * i0 + 12]);
            float4 v0 = *reinterpret_cast<const float4*>(&vals[i0]);
            float4 v1 = *reinterpret_cast<const float4*>(&vals[i0 + 4]);
            put(a.y, a.x, v0.x);
            put(a.w, a.z, v0.y);
            put(b.y, b.x, v0.z);
            put(b.w, b.z, v0.w);
            put(c.y, c.x, v1.x);
            put(c.w, c.z, v1.y);
            put(d.y, d.x, v1.z);
            put(d.w, d.z, v1.w);
        } else {
            for (int i = i0; i < NNZ; i++)
                put(nz[2 * i + 1], nz[2 * i], vals[i]);
        }
    } else {
        // ---- transpose tile: x [B,K] fp32 -> xT [K,B] fp16 ----
        __shared__ float s[32][66];
        const int lane = tid & 31;
        const int w    = tid >> 5;       // 8 warps
        int tb = blockIdx.x;
        int rb = (tb % 625) * 32;        // input-dim base
        int bb = (tb / 625) * 64;        // batch base (1024/64 = 16)
#pragma unroll
        for (int j = 0; j < 8; j++) {
            int b = w * 8 + j;
            s[lane][b] = x[(size_t)(bb + b) * INPUT_DIM + rb + lane];
        }
        __syncthreads();
#pragma unroll
        for (int j = 0; j < 4; j++) {
            int row = w + j * 8;
            int b0  = lane * 2;
            __half2 h = __floats2half2_rn(s[row][b0], s[row][b0 + 1]);
            *reinterpret_cast<__half2*>(&g_xT[(size_t)(rb + row) * BATCH + bb + b0]) = h;
        }
    }
}

// ------- 2. spmm: software-pipelined gathers (R11 hot loop, untouched) -----------
#define LOADQ(Q01, Q23, J)                                             \
    Q01 = *reinterpret_cast<int4*>(&s_rv[J]);                          \
    Q23 = *reinterpret_cast<int4*>(&s_rv[(J) + 2]);

#define LOADD(D0, D1, D2, D3, Q01, Q23)                                \
    D0 = xp[Q01.x * (BATCH / 8) + t];                                  \
    D1 = xp[Q01.z * (BATCH / 8) + t];                                  \
    D2 = xp[Q23.x * (BATCH / 8) + t];                                  \
    D3 = xp[Q23.z * (BATCH / 8) + t];

#define FMAG(Q01, Q23, D0, D1, D2, D3)                                        \
    {                                                                         \
        __half2 v0 = *reinterpret_cast<__half2*>(&Q01.y);                     \
        __half2 v1 = *reinterpret_cast<__half2*>(&Q01.w);                     \
        __half2 v2 = *reinterpret_cast<__half2*>(&Q23.y);                     \
        __half2 v3 = *reinterpret_cast<__half2*>(&Q23.w);                     \
        __half2 px = __hmul2(*reinterpret_cast<__half2*>(&D0.x), v0);         \
        __half2 py = __hmul2(*reinterpret_cast<__half2*>(&D0.y), v0);         \
        __half2 pz = __hmul2(*reinterpret_cast<__half2*>(&D0.z), v0);         \
        __half2 pw = __hmul2(*reinterpret_cast<__half2*>(&D0.w), v0);         \
        px = __hfma2(*reinterpret_cast<__half2*>(&D1.x), v1, px);             \
        py = __hfma2(*reinterpret_cast<__half2*>(&D1.y), v1, py);             \
        pz = __hfma2(*reinterpret_cast<__half2*>(&D1.z), v1, pz);             \
        pw = __hfma2(*reinterpret_cast<__half2*>(&D1.w), v1, pw);             \
        px = __hfma2(*reinterpret_cast<__half2*>(&D2.x), v2, px);             \
        py = __hfma2(*reinterpret_cast<__half2*>(&D2.y), v2, py);             \
        pz = __hfma2(*reinterpret_cast<__half2*>(&D2.z), v2, pz);             \
        pw = __hfma2(*reinterpret_cast<__half2*>(&D2.w), v2, pw);             \
        px = __hfma2(*reinterpret_cast<__half2*>(&D3.x), v3, px);             \
        py = __hfma2(*reinterpret_cast<__half2*>(&D3.y), v3, py);             \
        pz = __hfma2(*reinterpret_cast<__half2*>(&D3.z), v3, pz);             \
        pw = __hfma2(*reinterpret_cast<__half2*>(&D3.w), v3, pw);             \
        float2 fx = __half22float2(px);                                       \
        float2 fy = __half22float2(py);                                       \
        float2 fz = __half22float2(pz);                                       \
        float2 fw = __half22float2(pw);                                       \
        unsigned long long w0, w1, w2, w3;                                    \
        asm("mov.b64 %0, {%1, %2};" : "=l"(w0) : "f"(fx.x), "f"(fx.y));       \
        asm("mov.b64 %0, {%1, %2};" : "=l"(w1) : "f"(fy.x), "f"(fy.y));       \
        asm("mov.b64 %0, {%1, %2};" : "=l"(w2) : "f"(fz.x), "f"(fz.y));       \
        asm("mov.b64 %0, {%1, %2};" : "=l"(w3) : "f"(fw.x), "f"(fw.y));       \
        asm("add.rn.f32x2 %0, %0, %1;" : "+l"(a0) : "l"(w0));                 \
        asm("add.rn.f32x2 %0, %0, %1;" : "+l"(a1) : "l"(w1));                 \
        asm("add.rn.f32x2 %0, %0, %1;" : "+l"(a2) : "l"(w2));                 \
        asm("add.rn.f32x2 %0, %0, %1;" : "+l"(a3) : "l"(w3));                 \
    }

__global__ void __launch_bounds__(128) k_spmm(const float* __restrict__ bias) {
    const int u = blockIdx.x;
    const int t = threadIdx.x;
    __shared__ int2 s_rv[256];

    const int cnt = min(g_col_cnt[u], CAP);
    const int2* __restrict__ bucket = &g_rv[(size_t)u * CAP];

    unsigned long long a0 = 0, a1 = 0, a2 = 0, a3 = 0;   // packed f32x2 accumulators
    const uint4* __restrict__ xp = reinterpret_cast<const uint4*>(g_xT);

    for (int base = 0; base < cnt; base += 256) {
        int n = cnt - base;
        s_rv[t]       = (t < n)       ? bucket[base + t]       : make_int2(0, 0);
        s_rv[t + 128] = (t + 128 < n) ? bucket[base + t + 128] : make_int2(0, 0);
        __syncthreads();
        int mc = (min(256, n) + 7) & ~7;      // multiple of 8; pads contribute 0

        int4  qA01, qA23, qB01, qB23;
        uint4 dA0, dA1, dA2, dA3, dB0, dB1, dB2, dB3;
        LOADQ(qA01, qA23, 0)
        LOADD(dA0, dA1, dA2, dA3, qA01, qA23)
        for (int i = 0; i < mc; i += 8) {
            LOADQ(qB01, qB23, i + 4)
            LOADD(dB0, dB1, dB2, dB3, qB01, qB23)
            FMAG(qA01, qA23, dA0, dA1, dA2, dA3)
            int ja = (i + 8) & 255;           // s_rv fully initialized, safe
            LOADQ(qA01, qA23, ja)
            LOADD(dA0, dA1, dA2, dA3, qA01, qA23)
            FMAG(qB01, qB23, dB0, dB1, dB2, dB3)
        }
        __syncthreads();
    }

    float b = bias[u];
    float2 f0, f1, f2, f3;
    asm("mov.b64 {%0, %1}, %2;" : "=f"(f0.x), "=f"(f0.y) : "l"(a0));
    asm("mov.b64 {%0, %1}, %2;" : "=f"(f1.x), "=f"(f1.y) : "l"(a1));
    asm("mov.b64 {%0, %1}, %2;" : "=f"(f2.x), "=f"(f2.y) : "l"(a2));
    asm("mov.b64 {%0, %1}, %2;" : "=f"(f3.x), "=f"(f3.y) : "l"(a3));
    float4 o0, o1;
    o0.x = tanhf(f0.x + b);  o0.y = tanhf(f0.y + b);
    o0.z = tanhf(f1.x + b);  o0.w = tanhf(f1.y + b);
    o1.x = tanhf(f2.x + b);  o1.y = tanhf(f2.y + b);
    o1.z = tanhf(f3.x + b);  o1.w = tanhf(f3.y + b);
    float* op = &g_outT[(size_t)u * BATCH + t * 8];
    *reinterpret_cast<float4*>(op)     = o0;
    *reinterpret_cast<float4*>(op + 4) = o1;
}

// ---------------- 3. transpose outT [U,B] -> out [B,U] ----------------
__global__ void __launch_bounds__(256) k_txpose_out(float* __restrict__ out) {
    __shared__ float s[32][33];
    int ub = blockIdx.x * 32;
    int bb = blockIdx.y * 32;
    int tx = threadIdx.x, ty = threadIdx.y;
#pragma unroll
    for (int j = 0; j < 32; j += 8)
        s[ty + j][tx] = g_outT[(size_t)(ub + ty + j) * BATCH + bb + tx];
    __syncthreads();
#pragma unroll
    for (int j = 0; j < 32; j += 8)
        out[(size_t)(bb + ty + j) * UNITS + ub + tx] = s[tx][ty + j];
}

// ---------------- launch ----------------
extern "C" void kernel_launch(void* const* d_in, const int* in_sizes, int n_in,
                              void* d_out, int out_size) {
    const float* x    = (const float*)d_in[0];
    const float* kv   = (const float*)d_in[1];
    const float* bias = (const float*)d_in[2];
    const int*   nz   = (const int*)d_in[3];
    float* out = (float*)d_out;

    // zero bucket counters via a capturable memset node
    void* cnt_ptr = nullptr;
    cudaGetSymbolAddress(&cnt_ptr, g_col_cnt);
    cudaMemsetAsync(cnt_ptr, 0, UNITS * sizeof(int));

    dim3 tb(32, 8);
    k_prologue<<<NB_TXP + NB_SCAT, tb>>>(x, nz, kv);
    k_spmm<<<UNITS, 128>>>(bias);
    k_txpose_out<<<dim3(UNITS / 32, BATCH / 32), tb>>>(out);
}

// round 16
// speedup vs baseline: 1.3777x; 1.0913x over previous
#include <cuda_runtime.h>
#include <cuda_fp16.h>

#define INPUT_DIM 20000
#define UNITS     4096
#define NNZ       800000
#define BATCH     1024
#define CAP       320          // max nnz per column (Poisson(195), 9-sigma headroom)
#define NB_SCAT   391          // ceil(NNZ / 8 / 256) scatter blocks (head of grid)

// ---------------- scratch (no allocations allowed) ----------------
__device__ int    g_col_cnt[UNITS];                  // bucket fill counters
__device__ int2   g_rv[(size_t)UNITS * CAP];         // fixed-stride buckets, 10.5 MB
__device__ __half g_xT[(size_t)INPUT_DIM * BATCH];   // 41 MB, L2-resident
__device__ float  g_outT[(size_t)UNITS * BATCH];     // 16.8 MB

// ---------------- 1. fused prologue: scatter blocks + transpose tiles ------------
// blocks [0, NB_SCAT): bucket scatter (latency-bound, hidden under transpose)
// blocks [NB_SCAT, NB_SCAT + 10000): 32 input-rows x 64 batch transpose tiles
__device__ __forceinline__ int pack_h2(float v) {
    unsigned short h = __half_as_ushort(__float2half_rn(v));
    return (int)(((unsigned)h << 16) | (unsigned)h);
}

__device__ __forceinline__ void put(int col, int row, float v) {
    int p = atomicAdd(&g_col_cnt[col], 1);
    if (p < CAP) g_rv[(size_t)col * CAP + p] = make_int2(row, pack_h2(v));
}

__global__ void __launch_bounds__(256) k_prologue(const float* __restrict__ x,
                                                  const int*   __restrict__ nz,
                                                  const float* __restrict__ vals) {
    const int tid  = threadIdx.y * 32 + threadIdx.x;

    if (blockIdx.x < NB_SCAT) {
        // ---- scatter into fixed-stride buckets: 8 nnz/thread ----
        int i0 = (blockIdx.x * 256 + tid) * 8;
        if (i0 + 7 < NNZ) {
            int4 a = *reinterpret_cast<const int4*>(&nz[2 * i0]);
            int4 b = *reinterpret_cast<const int4*>(&nz[2 * i0 + 4]);
            int4 c = *reinterpret_cast<const int4*>(&nz[2 * i0 + 8]);
            int4 d = *reinterpret_cast<const int4*>(&nz[2 * i0 + 12]);
            float4 v0 = *reinterpret_cast<const float4*>(&vals[i0]);
            float4 v1 = *reinterpret_cast<const float4*>(&vals[i0 + 4]);
            put(a.y, a.x, v0.x);
            put(a.w, a.z, v0.y);
            put(b.y, b.x, v0.z);
            put(b.w, b.z, v0.w);
            put(c.y, c.x, v1.x);
            put(c.w, c.z, v1.y);
            put(d.y, d.x, v1.z);
            put(d.w, d.z, v1.w);
        } else {
            for (int i = i0; i < NNZ; i++)
                put(nz[2 * i + 1], nz[2 * i], vals[i]);
        }
    } else {
        // ---- transpose tile: x [B,K] fp32 -> xT [K,B] fp16 ----
        __shared__ float s[32][65];      // pad 65: float4 fan-out hits 32 banks
        const int lane = tid & 31;
        const int w    = tid >> 5;       // 8 warps
        int tb = blockIdx.x - NB_SCAT;
        int rb = (tb % 625) * 32;        // input-dim base
        int bb = (tb / 625) * 64;        // batch base (1024/64 = 16)
#pragma unroll
        for (int h = 0; h < 2; h++) {
            int idx = tid + h * 256;     // 0..511
            int q   = idx & 7;           // k-chunk (4 floats)
            int b   = idx >> 3;          // batch row 0..63
            float4 v = *reinterpret_cast<const float4*>(
                &x[(size_t)(bb + b) * INPUT_DIM + rb + 4 * q]);
            s[4 * q + 0][b] = v.x;
            s[4 * q + 1][b] = v.y;
            s[4 * q + 2][b] = v.z;
            s[4 * q + 3][b] = v.w;
        }
        __syncthreads();
#pragma unroll
        for (int j = 0; j < 4; j++) {
            int row = w + j * 8;
            int b0  = lane * 2;
            __half2 h = __floats2half2_rn(s[row][b0], s[row][b0 + 1]);
            *reinterpret_cast<__half2*>(&g_xT[(size_t)(rb + row) * BATCH + bb + b0]) = h;
        }
    }
}

// ------- 2. spmm: software-pipelined gathers (R6/R11 hot loop, untouched) --------
#define LOADQ(Q01, Q23, J)                                             \
    Q01 = *reinterpret_cast<int4*>(&s_rv[J]);                          \
    Q23 = *reinterpret_cast<int4*>(&s_rv[(J) + 2]);

#define LOADD(D0, D1, D2, D3, Q01, Q23)                                \
    D0 = xp[Q01.x * (BATCH / 8) + t];                                  \
    D1 = xp[Q01.z * (BATCH / 8) + t];                                  \
    D2 = xp[Q23.x * (BATCH / 8) + t];                                  \
    D3 = xp[Q23.z * (BATCH / 8) + t];

#define FMAG(Q01, Q23, D0, D1, D2, D3)                                        \
    {                                                                         \
        __half2 v0 = *reinterpret_cast<__half2*>(&Q01.y);                     \
        __half2 v1 = *reinterpret_cast<__half2*>(&Q01.w);                     \
        __half2 v2 = *reinterpret_cast<__half2*>(&Q23.y);                     \
        __half2 v3 = *reinterpret_cast<__half2*>(&Q23.w);                     \
        __half2 px = __hmul2(*reinterpret_cast<__half2*>(&D0.x), v0);         \
        __half2 py = __hmul2(*reinterpret_cast<__half2*>(&D0.y), v0);         \
        __half2 pz = __hmul2(*reinterpret_cast<__half2*>(&D0.z), v0);         \
        __half2 pw = __hmul2(*reinterpret_cast<__half2*>(&D0.w), v0);         \
        px = __hfma2(*reinterpret_cast<__half2*>(&D1.x), v1, px);             \
        py = __hfma2(*reinterpret_cast<__half2*>(&D1.y), v1, py);             \
        pz = __hfma2(*reinterpret_cast<__half2*>(&D1.z), v1, pz);             \
        pw = __hfma2(*reinterpret_cast<__half2*>(&D1.w), v1, pw);             \
        px = __hfma2(*reinterpret_cast<__half2*>(&D2.x), v2, px);             \
        py = __hfma2(*reinterpret_cast<__half2*>(&D2.y), v2, py);             \
        pz = __hfma2(*reinterpret_cast<__half2*>(&D2.z), v2, pz);             \
        pw = __hfma2(*reinterpret_cast<__half2*>(&D2.w), v2, pw);             \
        px = __hfma2(*reinterpret_cast<__half2*>(&D3.x), v3, px);             \
        py = __hfma2(*reinterpret_cast<__half2*>(&D3.y), v3, py);             \
        pz = __hfma2(*reinterpret_cast<__half2*>(&D3.z), v3, pz);             \
        pw = __hfma2(*reinterpret_cast<__half2*>(&D3.w), v3, pw);             \
        float2 fx = __half22float2(px);                                       \
        float2 fy = __half22float2(py);                                       \
        float2 fz = __half22float2(pz);                                       \
        float2 fw = __half22float2(pw);                                       \
        unsigned long long w0, w1, w2, w3;                                    \
        asm("mov.b64 %0, {%1, %2};" : "=l"(w0) : "f"(fx.x), "f"(fx.y));       \
        asm("mov.b64 %0, {%1, %2};" : "=l"(w1) : "f"(fy.x), "f"(fy.y));       \
        asm("mov.b64 %0, {%1, %2};" : "=l"(w2) : "f"(fz.x), "f"(fz.y));       \
        asm("mov.b64 %0, {%1, %2};" : "=l"(w3) : "f"(fw.x), "f"(fw.y));       \
        asm("add.rn.f32x2 %0, %0, %1;" : "+l"(a0) : "l"(w0));                 \
        asm("add.rn.f32x2 %0, %0, %1;" : "+l"(a1) : "l"(w1));                 \
        asm("add.rn.f32x2 %0, %0, %1;" : "+l"(a2) : "l"(w2));                 \
        asm("add.rn.f32x2 %0, %0, %1;" : "+l"(a3) : "l"(w3));                 \
    }

__global__ void __launch_bounds__(128) k_spmm(const float* __restrict__ bias) {
    const int u = blockIdx.x;
    const int t = threadIdx.x;
    __shared__ int2 s_rv[256];

    const int cnt = min(g_col_cnt[u], CAP);
    const int2* __restrict__ bucket = &g_rv[(size_t)u * CAP];

    unsigned long long a0 = 0, a1 = 0, a2 = 0, a3 = 0;   // packed f32x2 accumulators
    const uint4* __restrict__ xp = reinterpret_cast<const uint4*>(g_xT);

    for (int base = 0; base < cnt; base += 256) {
        int n = cnt - base;
        s_rv[t]       = (t < n)       ? bucket[base + t]       : make_int2(0, 0);
        s_rv[t + 128] = (t + 128 < n) ? bucket[base + t + 128] : make_int2(0, 0);
        __syncthreads();
        int mc = (min(256, n) + 7) & ~7;      // multiple of 8; pads contribute 0

        int4  qA01, qA23, qB01, qB23;
        uint4 dA0, dA1, dA2, dA3, dB0, dB1, dB2, dB3;
        LOADQ(qA01, qA23, 0)
        LOADD(dA0, dA1, dA2, dA3, qA01, qA23)
        for (int i = 0; i < mc; i += 8) {
            LOADQ(qB01, qB23, i + 4)
            LOADD(dB0, dB1, dB2, dB3, qB01, qB23)
            FMAG(qA01, qA23, dA0, dA1, dA2, dA3)
            int ja = (i + 8) & 255;           // s_rv fully initialized, safe
            LOADQ(qA01, qA23, ja)
            LOADD(dA0, dA1, dA2, dA3, qA01, qA23)
            FMAG(qB01, qB23, dB0, dB1, dB2, dB3)
        }
        __syncthreads();
    }

    float b = bias[u];
    float2 f0, f1, f2, f3;
    asm("mov.b64 {%0, %1}, %2;" : "=f"(f0.x), "=f"(f0.y) : "l"(a0));
    asm("mov.b64 {%0, %1}, %2;" : "=f"(f1.x), "=f"(f1.y) : "l"(a1));
    asm("mov.b64 {%0, %1}, %2;" : "=f"(f2.x), "=f"(f2.y) : "l"(a2));
    asm("mov.b64 {%0, %1}, %2;" : "=f"(f3.x), "=f"(f3.y) : "l"(a3));
    float4 o0, o1;
    o0.x = tanhf(f0.x + b);  o0.y = tanhf(f0.y + b);
    o0.z = tanhf(f1.x + b);  o0.w = tanhf(f1.y + b);
    o1.x = tanhf(f2.x + b);  o1.y = tanhf(f2.y + b);
    o1.z = tanhf(f3.x + b);  o1.w = tanhf(f3.y + b);
    float* op = &g_outT[(size_t)u * BATCH + t * 8];
    *reinterpret_cast<float4*>(op)     = o0;
    *reinterpret_cast<float4*>(op + 4) = o1;
}

// ---------------- 3. transpose outT [U,B] -> out [B,U] ----------------
__global__ void __launch_bounds__(256) k_txpose_out(float* __restrict__ out) {
    __shared__ float s[32][33];
    int ub = blockIdx.x * 32;
    int bb = blockIdx.y * 32;
    int tx = threadIdx.x, ty = threadIdx.y;
#pragma unroll
    for (int j = 0; j < 32; j += 8)
        s[ty + j][tx] = g_outT[(size_t)(ub + ty + j) * BATCH + bb + tx];
    __syncthreads();
#pragma unroll
    for (int j = 0; j < 32; j += 8)
        out[(size_t)(bb + ty + j) * UNITS + ub + tx] = s[tx][ty + j];
}

// ---------------- launch ----------------
extern "C" void kernel_launch(void* const* d_in, const int* in_sizes, int n_in,
                              void* d_out, int out_size) {
    const float* x    = (const float*)d_in[0];
    const float* kv   = (const float*)d_in[1];
    const float* bias = (const float*)d_in[2];
    const int*   nz   = (const int*)d_in[3];
    float* out = (float*)d_out;

    // zero bucket counters via a capturable memset node
    void* cnt_ptr = nullptr;
    cudaGetSymbolAddress(&cnt_ptr, g_col_cnt);
    cudaMemsetAsync(cnt_ptr, 0, UNITS * sizeof(int));

    dim3 tb(32, 8);
    k_prologue<<<NB_SCAT + 625 * (BATCH / 64), tb>>>(x, nz, kv);
    k_spmm<<<UNITS, 128>>>(bias);
    k_txpose_out<<<dim3(UNITS / 32, BATCH / 32), tb>>>(out);
}

// round 17
// speedup vs baseline: 1.3923x; 1.0106x over previous
#include <cuda_runtime.h>
#include <cuda_fp16.h>

#define INPUT_DIM 20000
#define UNITS     4096
#define NNZ       800000
#define BATCH     1024
#define CAP       320          // max nnz per column (Poisson(195), 9-sigma headroom)
#define NB_SCAT   391          // ceil(NNZ / 8 / 256) scatter blocks (head of grid)
#define NB_TXP    5000         // 625 * 8 transpose tiles (32 rows x 128 batch)

// ---------------- scratch (no allocations allowed) ----------------
__device__ int    g_col_cnt[UNITS];                  // bucket fill counters
__device__ int2   g_rv[(size_t)UNITS * CAP];         // fixed-stride buckets, 10.5 MB
__device__ __half g_xT[(size_t)INPUT_DIM * BATCH];   // 41 MB, L2-resident
__device__ float  g_outT[(size_t)UNITS * BATCH];     // 16.8 MB

// ---------------- 1. fused prologue: scatter blocks + transpose tiles ------------
// blocks [0, NB_SCAT): bucket scatter (latency-bound, hidden under transpose)
// blocks [NB_SCAT, NB_SCAT + NB_TXP): 32 rows x 128 batch transpose tiles,
// 4 independent float4 loads per thread (64 B in flight -> deeper DRAM MLP).
__device__ __forceinline__ int pack_h2(float v) {
    unsigned short h = __half_as_ushort(__float2half_rn(v));
    return (int)(((unsigned)h << 16) | (unsigned)h);
}

__device__ __forceinline__ void put(int col, int row, float v) {
    int p = atomicAdd(&g_col_cnt[col], 1);
    if (p < CAP) g_rv[(size_t)col * CAP + p] = make_int2(row, pack_h2(v));
}

__global__ void __launch_bounds__(256) k_prologue(const float* __restrict__ x,
                                                  const int*   __restrict__ nz,
                                                  const float* __restrict__ vals) {
    const int tid  = threadIdx.y * 32 + threadIdx.x;

    if (blockIdx.x < NB_SCAT) {
        // ---- scatter into fixed-stride buckets: 8 nnz/thread ----
        int i0 = (blockIdx.x * 256 + tid) * 8;
        if (i0 + 7 < NNZ) {
            int4 a = *reinterpret_cast<const int4*>(&nz[2 * i0]);
            int4 b = *reinterpret_cast<const int4*>(&nz[2 * i0 + 4]);
            int4 c = *reinterpret_cast<const int4*>(&nz[2 * i0 + 8]);
            int4 d = *reinterpret_cast<const int4*>(&nz[2 * i0 + 12]);
            float4 v0 = *reinterpret_cast<const float4*>(&vals[i0]);
            float4 v1 = *reinterpret_cast<const float4*>(&vals[i0 + 4]);
            put(a.y, a.x, v0.x);
            put(a.w, a.z, v0.y);
            put(b.y, b.x, v0.z);
            put(b.w, b.z, v0.w);
            put(c.y, c.x, v1.x);
            put(c.w, c.z, v1.y);
            put(d.y, d.x, v1.z);
            put(d.w, d.z, v1.w);
        } else {
            for (int i = i0; i < NNZ; i++)
                put(nz[2 * i + 1], nz[2 * i], vals[i]);
        }
    } else {
        // ---- transpose tile: x [B,K] fp32 -> xT [K,B] fp16, 32 x 128 ----
        __shared__ float s[32][129];     // pad 129: float4 fan-out conflict-free
        const int lane = tid & 31;
        const int w    = tid >> 5;       // 8 warps
        int tb = blockIdx.x - NB_SCAT;
        int rb = (tb % 625) * 32;        // input-dim base
        int bb = (tb / 625) * 128;       // batch base (1024/128 = 8)
        // load: 1024 float4 total; thread covers 4 (64 B in flight).
        // warp request = 8 k-chunks x 4 batch rows = 4 full 128B lines (512 B).
#pragma unroll
        for (int h = 0; h < 4; h++) {
            int idx = tid + h * 256;     // 0..1023
            int q   = idx & 7;           // k-chunk (4 floats)
            int b   = idx >> 3;          // batch row 0..127
            float4 v = *reinterpret_cast<const float4*>(
                &x[(size_t)(bb + b) * INPUT_DIM + rb + 4 * q]);
            s[4 * q + 0][b] = v.x;
            s[4 * q + 1][b] = v.y;
            s[4 * q + 2][b] = v.z;
            s[4 * q + 3][b] = v.w;
        }
        __syncthreads();
        // store: warp writes rows w, w+8, w+16, w+24; two 128B half2 stores/row
#pragma unroll
        for (int j = 0; j < 4; j++) {
            int row = w + j * 8;
            int b0  = lane * 2;
            __half2 h0 = __floats2half2_rn(s[row][b0],      s[row][b0 + 1]);
            __half2 h1 = __floats2half2_rn(s[row][64 + b0], s[row][64 + b0 + 1]);
            __half* dst = &g_xT[(size_t)(rb + row) * BATCH + bb];
            *reinterpret_cast<__half2*>(dst + b0)      = h0;
            *reinterpret_cast<__half2*>(dst + 64 + b0) = h1;
        }
    }
}

// ------- 2. spmm: software-pipelined gathers (R6/R11 hot loop, untouched) --------
#define LOADQ(Q01, Q23, J)                                             \
    Q01 = *reinterpret_cast<int4*>(&s_rv[J]);                          \
    Q23 = *reinterpret_cast<int4*>(&s_rv[(J) + 2]);

#define LOADD(D0, D1, D2, D3, Q01, Q23)                                \
    D0 = xp[Q01.x * (BATCH / 8) + t];                                  \
    D1 = xp[Q01.z * (BATCH / 8) + t];                                  \
    D2 = xp[Q23.x * (BATCH / 8) + t];                                  \
    D3 = xp[Q23.z * (BATCH / 8) + t];

#define FMAG(Q01, Q23, D0, D1, D2, D3)                                        \
    {                                                                         \
        __half2 v0 = *reinterpret_cast<__half2*>(&Q01.y);                     \
        __half2 v1 = *reinterpret_cast<__half2*>(&Q01.w);                     \
        __half2 v2 = *reinterpret_cast<__half2*>(&Q23.y);                     \
        __half2 v3 = *reinterpret_cast<__half2*>(&Q23.w);                     \
        __half2 px = __hmul2(*reinterpret_cast<__half2*>(&D0.x), v0);         \
        __half2 py = __hmul2(*reinterpret_cast<__half2*>(&D0.y), v0);         \
        __half2 pz = __hmul2(*reinterpret_cast<__half2*>(&D0.z), v0);         \
        __half2 pw = __hmul2(*reinterpret_cast<__half2*>(&D0.w), v0);         \
        px = __hfma2(*reinterpret_cast<__half2*>(&D1.x), v1, px);             \
        py = __hfma2(*reinterpret_cast<__half2*>(&D1.y), v1, py);             \
        pz = __hfma2(*reinterpret_cast<__half2*>(&D1.z), v1, pz);             \
        pw = __hfma2(*reinterpret_cast<__half2*>(&D1.w), v1, pw);             \
        px = __hfma2(*reinterpret_cast<__half2*>(&D2.x), v2, px);             \
        py = __hfma2(*reinterpret_cast<__half2*>(&D2.y), v2, py);             \
        pz = __hfma2(*reinterpret_cast<__half2*>(&D2.z), v2, pz);             \
        pw = __hfma2(*reinterpret_cast<__half2*>(&D2.w), v2, pw);             \
        px = __hfma2(*reinterpret_cast<__half2*>(&D3.x), v3, px);             \
        py = __hfma2(*reinterpret_cast<__half2*>(&D3.y), v3, py);             \
        pz = __hfma2(*reinterpret_cast<__half2*>(&D3.z), v3, pz);             \
        pw = __hfma2(*reinterpret_cast<__half2*>(&D3.w), v3, pw);             \
        float2 fx = __half22float2(px);                                       \
        float2 fy = __half22float2(py);                                       \
        float2 fz = __half22float2(pz);                                       \
        float2 fw = __half22float2(pw);                                       \
        unsigned long long w0, w1, w2, w3;                                    \
        asm("mov.b64 %0, {%1, %2};" : "=l"(w0) : "f"(fx.x), "f"(fx.y));       \
        asm("mov.b64 %0, {%1, %2};" : "=l"(w1) : "f"(fy.x), "f"(fy.y));       \
        asm("mov.b64 %0, {%1, %2};" : "=l"(w2) : "f"(fz.x), "f"(fz.y));       \
        asm("mov.b64 %0, {%1, %2};" : "=l"(w3) : "f"(fw.x), "f"(fw.y));       \
        asm("add.rn.f32x2 %0, %0, %1;" : "+l"(a0) : "l"(w0));                 \
        asm("add.rn.f32x2 %0, %0, %1;" : "+l"(a1) : "l"(w1));                 \
        asm("add.rn.f32x2 %0, %0, %1;" : "+l"(a2) : "l"(w2));                 \
        asm("add.rn.f32x2 %0, %0, %1;" : "+l"(a3) : "l"(w3));                 \
    }

__global__ void __launch_bounds__(128) k_spmm(const float* __restrict__ bias) {
    const int u = blockIdx.x;
    const int t = threadIdx.x;
    __shared__ int2 s_rv[256];

    const int cnt = min(g_col_cnt[u], CAP);
    const int2* __restrict__ bucket = &g_rv[(size_t)u * CAP];

    unsigned long long a0 = 0, a1 = 0, a2 = 0, a3 = 0;   // packed f32x2 accumulators
    const uint4* __restrict__ xp = reinterpret_cast<const uint4*>(g_xT);

    for (int base = 0; base < cnt; base += 256) {
        int n = cnt - base;
        s_rv[t]       = (t < n)       ? bucket[base + t]       : make_int2(0, 0);
        s_rv[t + 128] = (t + 128 < n) ? bucket[base + t + 128] : make_int2(0, 0);
        __syncthreads();
        int mc = (min(256, n) + 7) & ~7;      // multiple of 8; pads contribute 0

        int4  qA01, qA23, qB01, qB23;
        uint4 dA0, dA1, dA2, dA3, dB0, dB1, dB2, dB3;
        LOADQ(qA01, qA23, 0)
        LOADD(dA0, dA1, dA2, dA3, qA01, qA23)
        for (int i = 0; i < mc; i += 8) {
            LOADQ(qB01, qB23, i + 4)
            LOADD(dB0, dB1, dB2, dB3, qB01, qB23)
            FMAG(qA01, qA23, dA0, dA1, dA2, dA3)
            int ja = (i + 8) & 255;           // s_rv fully initialized, safe
            LOADQ(qA01, qA23, ja)
            LOADD(dA0, dA1, dA2, dA3, qA01, qA23)
            FMAG(qB01, qB23, dB0, dB1, dB2, dB3)
        }
        __syncthreads();
    }

    float b = bias[u];
    float2 f0, f1, f2, f3;
    asm("mov.b64 {%0, %1}, %2;" : "=f"(f0.x), "=f"(f0.y) : "l"(a0));
    asm("mov.b64 {%0, %1}, %2;" : "=f"(f1.x), "=f"(f1.y) : "l"(a1));
    asm("mov.b64 {%0, %1}, %2;" : "=f"(f2.x), "=f"(f2.y) : "l"(a2));
    asm("mov.b64 {%0, %1}, %2;" : "=f"(f3.x), "=f"(f3.y) : "l"(a3));
    float4 o0, o1;
    o0.x = tanhf(f0.x + b);  o0.y = tanhf(f0.y + b);
    o0.z = tanhf(f1.x + b);  o0.w = tanhf(f1.y + b);
    o1.x = tanhf(f2.x + b);  o1.y = tanhf(f2.y + b);
    o1.z = tanhf(f3.x + b);  o1.w = tanhf(f3.y + b);
    float* op = &g_outT[(size_t)u * BATCH + t * 8];
    *reinterpret_cast<float4*>(op)     = o0;
    *reinterpret_cast<float4*>(op + 4) = o1;
}

// ---------------- 3. transpose outT [U,B] -> out [B,U] ----------------
__global__ void __launch_bounds__(256) k_txpose_out(float* __restrict__ out) {
    __shared__ float s[32][33];
    int ub = blockIdx.x * 32;
    int bb = blockIdx.y * 32;
    int tx = threadIdx.x, ty = threadIdx.y;
#pragma unroll
    for (int j = 0; j < 32; j += 8)
        s[ty + j][tx] = g_outT[(size_t)(ub + ty + j) * BATCH + bb + tx];
    __syncthreads();
#pragma unroll
    for (int j = 0; j < 32; j += 8)
        out[(size_t)(bb + ty + j) * UNITS + ub + tx] = s[tx][ty + j];
}

// ---------------- launch ----------------
extern "C" void kernel_launch(void* const* d_in, const int* in_sizes, int n_in,
                              void* d_out, int out_size) {
    const float* x    = (const float*)d_in[0];
    const float* kv   = (const float*)d_in[1];
    const float* bias = (const float*)d_in[2];
    const int*   nz   = (const int*)d_in[3];
    float* out = (float*)d_out;

    // zero bucket counters via a capturable memset node
    void* cnt_ptr = nullptr;
    cudaGetSymbolAddress(&cnt_ptr, g_col_cnt);
    cudaMemsetAsync(cnt_ptr, 0, UNITS * sizeof(int));

    dim3 tb(32, 8);
    k_prologue<<<NB_SCAT + NB_TXP, tb>>>(x, nz, kv);
    k_spmm<<<UNITS, 128>>>(bias);
    k_txpose_out<<<dim3(UNITS / 32, BATCH / 32), tb>>>(out);
}